// round 2
// baseline (speedup 1.0000x reference)
#include <cuda_runtime.h>
#include <math.h>

#define B_  2
#define S_  2048
#define D_  1024
#define H_  16
#define HD_ 64

// Scratch for projected Q/K/V in [b,h,s,hd] layout (16.8 MB each).
__device__ float g_Q[B_*H_*S_*HD_];
__device__ float g_K[B_*H_*S_*HD_];
__device__ float g_V[B_*H_*S_*HD_];

// ---------------------------------------------------------------------------
// Projection GEMM: out[m][n] = sum_k A[m][k] * W[n][k]   (x @ w.T)
// M=4096 (b*s), N=1024 (h*hd), K=1024. 64x64 tile, BK=16, 256 thr, 4x4 micro.
// Output written directly in [b,h,s,hd] layout (tile width == head dim 64).
// ---------------------------------------------------------------------------
__global__ __launch_bounds__(256) void proj_kernel(const float* __restrict__ A,
                                                   const float* __restrict__ W,
                                                   float* __restrict__ out)
{
    __shared__ float As[16][68];   // As[k][m]
    __shared__ float Bs[16][68];   // Bs[k][n]
    const int tid = threadIdx.x;
    const int ty = tid >> 4, tx = tid & 15;
    const int m0 = blockIdx.y * 64;
    const int n0 = blockIdx.x * 64;
    const int lr = tid >> 2;            // 0..63: tile row to load
    const int k4 = (tid & 3) << 2;      // 0,4,8,12: k offset (float4)

    float acc[4][4];
    #pragma unroll
    for (int i = 0; i < 4; i++)
        #pragma unroll
        for (int j = 0; j < 4; j++) acc[i][j] = 0.f;

    for (int k0 = 0; k0 < D_; k0 += 16) {
        float4 av = *reinterpret_cast<const float4*>(&A[(m0 + lr) * D_ + k0 + k4]);
        float4 bv = *reinterpret_cast<const float4*>(&W[(n0 + lr) * D_ + k0 + k4]);
        As[k4 + 0][lr] = av.x; As[k4 + 1][lr] = av.y;
        As[k4 + 2][lr] = av.z; As[k4 + 3][lr] = av.w;
        Bs[k4 + 0][lr] = bv.x; Bs[k4 + 1][lr] = bv.y;
        Bs[k4 + 2][lr] = bv.z; Bs[k4 + 3][lr] = bv.w;
        __syncthreads();
        #pragma unroll
        for (int kk = 0; kk < 16; kk++) {
            float4 a = *reinterpret_cast<const float4*>(&As[kk][ty * 4]);
            float4 b = *reinterpret_cast<const float4*>(&Bs[kk][tx * 4]);
            float ar[4] = {a.x, a.y, a.z, a.w};
            float br[4] = {b.x, b.y, b.z, b.w};
            #pragma unroll
            for (int i = 0; i < 4; i++)
                #pragma unroll
                for (int j = 0; j < 4; j++)
                    acc[i][j] = fmaf(ar[i], br[j], acc[i][j]);
        }
        __syncthreads();
    }

    const int h = n0 >> 6;  // tile width 64 == head dim
    #pragma unroll
    for (int i = 0; i < 4; i++) {
        int m = m0 + ty * 4 + i;
        int b = m >> 11;            // / S_
        int s = m & (S_ - 1);
        float4 v = make_float4(acc[i][0], acc[i][1], acc[i][2], acc[i][3]);
        *reinterpret_cast<float4*>(&out[((b * H_ + h) * S_ + s) * HD_ + tx * 4]) = v;
    }
}

// ---------------------------------------------------------------------------
// Attention with the reference's quirky mask: upper triangle is ZEROED (not
// -inf) before softmax, so masked positions contribute exp(0-m)/Z.
// Implemented as streaming (flash) softmax over the FULL sequence with
// modified score s' = (k<=q) ? s*scale : 0.
// Block: 256 thr (16x16), handles one (b,h) and 64 query rows; loops over
// all 32 key tiles of 64. smem tiles 64x68 fp32: Qs[d][q], Ks[d][k],
// Vs[k][d], Ps[k][q].
// ---------------------------------------------------------------------------
__global__ __launch_bounds__(256) void attn_kernel(float* __restrict__ out)
{
    extern __shared__ float sm[];
    float* Qs = sm;                 // [64][68] Qs[d][q]
    float* Ks = sm + 64 * 68;       // [64][68] Ks[d][k]
    float* Vs = sm + 2 * 64 * 68;   // [64][68] Vs[k][d]
    float* Ps = sm + 3 * 64 * 68;   // [64][68] Ps[k][q]

    const int tid = threadIdx.x;
    const int ty = tid >> 4, tx = tid & 15;
    const int bh = blockIdx.y;      // b*H + h
    const int qt = blockIdx.x;      // query tile
    const float* Qp = g_Q + (size_t)bh * S_ * HD_;
    const float* Kp = g_K + (size_t)bh * S_ * HD_;
    const float* Vp = g_V + (size_t)bh * S_ * HD_;

    const int lr = tid >> 2;        // 0..63 row to load
    const int c4 = tid & 3;         // 0..3

    // Load Q tile transposed: Qs[d][q]
    #pragma unroll
    for (int j = 0; j < 4; j++) {
        int dcol = (c4 + 4 * j) * 4;   // 0..60 step 4
        float4 v = *reinterpret_cast<const float4*>(&Qp[(qt * 64 + lr) * HD_ + dcol]);
        Qs[(dcol + 0) * 68 + lr] = v.x;
        Qs[(dcol + 1) * 68 + lr] = v.y;
        Qs[(dcol + 2) * 68 + lr] = v.z;
        Qs[(dcol + 3) * 68 + lr] = v.w;
    }

    float m_i[4], l_i[4], o[4][4];
    #pragma unroll
    for (int i = 0; i < 4; i++) {
        m_i[i] = -1e30f;
        l_i[i] = 0.f;
        #pragma unroll
        for (int j = 0; j < 4; j++) o[i][j] = 0.f;
    }
    __syncthreads();

    const float scale = 0.125f;  // 1/sqrt(64)
    const int qbase = qt * 64 + ty * 4;

    for (int kt = 0; kt < S_ / 64; kt++) {
        // Load K (transposed) and V (natural) tiles
        #pragma unroll
        for (int j = 0; j < 4; j++) {
            int dcol = (c4 + 4 * j) * 4;
            float4 kv = *reinterpret_cast<const float4*>(&Kp[(kt * 64 + lr) * HD_ + dcol]);
            Ks[(dcol + 0) * 68 + lr] = kv.x;
            Ks[(dcol + 1) * 68 + lr] = kv.y;
            Ks[(dcol + 2) * 68 + lr] = kv.z;
            Ks[(dcol + 3) * 68 + lr] = kv.w;
            float4 vv = *reinterpret_cast<const float4*>(&Vp[(kt * 64 + lr) * HD_ + dcol]);
            *reinterpret_cast<float4*>(&Vs[lr * 68 + dcol]) = vv;
        }
        __syncthreads();

        // Scores: sc[i][j] = Q[q_i] . K[k_j]
        float sc[4][4];
        #pragma unroll
        for (int i = 0; i < 4; i++)
            #pragma unroll
            for (int j = 0; j < 4; j++) sc[i][j] = 0.f;
        #pragma unroll 16
        for (int kk = 0; kk < 64; kk++) {
            float4 a = *reinterpret_cast<const float4*>(&Qs[kk * 68 + ty * 4]);
            float4 b = *reinterpret_cast<const float4*>(&Ks[kk * 68 + tx * 4]);
            float ar[4] = {a.x, a.y, a.z, a.w};
            float br[4] = {b.x, b.y, b.z, b.w};
            #pragma unroll
            for (int i = 0; i < 4; i++)
                #pragma unroll
                for (int j = 0; j < 4; j++)
                    sc[i][j] = fmaf(ar[i], br[j], sc[i][j]);
        }

        const int kbase = kt * 64 + tx * 4;

        // Mask (zero, not -inf) + scale; streaming softmax update
        #pragma unroll
        for (int i = 0; i < 4; i++) {
            float rm = -1e30f;
            #pragma unroll
            for (int j = 0; j < 4; j++) {
                float v = (kbase + j <= qbase + i) ? sc[i][j] * scale : 0.f;
                sc[i][j] = v;
                rm = fmaxf(rm, v);
            }
            // reduce max across the 16 lanes owning this row
            rm = fmaxf(rm, __shfl_xor_sync(0xffffffffu, rm, 1));
            rm = fmaxf(rm, __shfl_xor_sync(0xffffffffu, rm, 2));
            rm = fmaxf(rm, __shfl_xor_sync(0xffffffffu, rm, 4));
            rm = fmaxf(rm, __shfl_xor_sync(0xffffffffu, rm, 8));
            float mnew = fmaxf(m_i[i], rm);
            float corr = __expf(m_i[i] - mnew);
            float rs = 0.f;
            #pragma unroll
            for (int j = 0; j < 4; j++) {
                float p = __expf(sc[i][j] - mnew);
                sc[i][j] = p;
                rs += p;
            }
            rs += __shfl_xor_sync(0xffffffffu, rs, 1);
            rs += __shfl_xor_sync(0xffffffffu, rs, 2);
            rs += __shfl_xor_sync(0xffffffffu, rs, 4);
            rs += __shfl_xor_sync(0xffffffffu, rs, 8);
            l_i[i] = l_i[i] * corr + rs;
            m_i[i] = mnew;
            #pragma unroll
            for (int j = 0; j < 4; j++) o[i][j] *= corr;
        }

        // Stage P (Ps[k][q]) for the PV GEMM
        #pragma unroll
        for (int i = 0; i < 4; i++)
            #pragma unroll
            for (int j = 0; j < 4; j++)
                Ps[(tx * 4 + j) * 68 + ty * 4 + i] = sc[i][j];
        __syncthreads();

        // O += P * V
        #pragma unroll 16
        for (int kk = 0; kk < 64; kk++) {
            float4 a = *reinterpret_cast<const float4*>(&Ps[kk * 68 + ty * 4]);
            float4 b = *reinterpret_cast<const float4*>(&Vs[kk * 68 + tx * 4]);
            float ar[4] = {a.x, a.y, a.z, a.w};
            float br[4] = {b.x, b.y, b.z, b.w};
            #pragma unroll
            for (int i = 0; i < 4; i++)
                #pragma unroll
                for (int j = 0; j < 4; j++)
                    o[i][j] = fmaf(ar[i], br[j], o[i][j]);
        }
        __syncthreads();
    }

    // Epilogue: divide by l, write to [b, s, h*hd + d]
    const int b = bh / H_;
    const int h = bh % H_;
    #pragma unroll
    for (int i = 0; i < 4; i++) {
        int s = qt * 64 + ty * 4 + i;
        float inv = 1.f / l_i[i];
        float4 v = make_float4(o[i][0] * inv, o[i][1] * inv,
                               o[i][2] * inv, o[i][3] * inv);
        *reinterpret_cast<float4*>(&out[((size_t)(b * S_ + s)) * D_ + h * HD_ + tx * 4]) = v;
    }
}

// ---------------------------------------------------------------------------
extern "C" void kernel_launch(void* const* d_in, const int* in_sizes, int n_in,
                              void* d_out, int out_size)
{
    const float* q  = (const float*)d_in[0];
    const float* k  = (const float*)d_in[1];
    const float* v  = (const float*)d_in[2];
    const float* wq = (const float*)d_in[3];
    const float* wk = (const float*)d_in[4];
    const float* wv = (const float*)d_in[5];
    float* out = (float*)d_out;

    void *pQ, *pK, *pV;
    cudaGetSymbolAddress(&pQ, g_Q);
    cudaGetSymbolAddress(&pK, g_K);
    cudaGetSymbolAddress(&pV, g_V);

    dim3 pgrid(D_ / 64, (B_ * S_) / 64);   // (16, 64)
    proj_kernel<<<pgrid, 256>>>(q, wq, (float*)pQ);
    proj_kernel<<<pgrid, 256>>>(k, wk, (float*)pK);
    proj_kernel<<<pgrid, 256>>>(v, wv, (float*)pV);

    const int smem_bytes = 4 * 64 * 68 * 4;  // 69632
    cudaFuncSetAttribute(attn_kernel, cudaFuncAttributeMaxDynamicSharedMemorySize,
                         smem_bytes);
    attn_kernel<<<dim3(S_ / 64, B_ * H_), 256, smem_bytes>>>(out);
}

// round 4
// speedup vs baseline: 1.0933x; 1.0933x over previous
#include <cuda_runtime.h>
#include <cuda_bf16.h>
#include <mma.h>
#include <cstdint>
#include <math.h>

using namespace nvcuda;

#define B_  2
#define S_  2048
#define D_  1024
#define H_  16
#define HD_ 64

// Scratch: projected Q/K/V in [b,h,s,hd] layout + V suffix sums.
__device__ float g_Q[B_*H_*S_*HD_];
__device__ float g_K[B_*H_*S_*HD_];
__device__ float g_V[B_*H_*S_*HD_];
__device__ float g_S[B_*H_*S_*HD_];   // SufV[bh][q][d] = sum_{k>q} V[bh][k][d]

// ---------------------------------------------------------------------------
// helpers: split fp32 -> (hi, lo) bf16 pairs packed as uint2 (4 values)
// ---------------------------------------------------------------------------
__device__ __forceinline__ void split4(float4 a, uint2& hv, uint2& lv) {
    __nv_bfloat16 h0 = __float2bfloat16(a.x);
    __nv_bfloat16 h1 = __float2bfloat16(a.y);
    __nv_bfloat16 h2 = __float2bfloat16(a.z);
    __nv_bfloat16 h3 = __float2bfloat16(a.w);
    __nv_bfloat16 l0 = __float2bfloat16(a.x - __bfloat162float(h0));
    __nv_bfloat16 l1 = __float2bfloat16(a.y - __bfloat162float(h1));
    __nv_bfloat16 l2 = __float2bfloat16(a.z - __bfloat162float(h2));
    __nv_bfloat16 l3 = __float2bfloat16(a.w - __bfloat162float(h3));
    hv = make_uint2(((uint32_t)__bfloat16_as_ushort(h1) << 16) | __bfloat16_as_ushort(h0),
                    ((uint32_t)__bfloat16_as_ushort(h3) << 16) | __bfloat16_as_ushort(h2));
    lv = make_uint2(((uint32_t)__bfloat16_as_ushort(l1) << 16) | __bfloat16_as_ushort(l0),
                    ((uint32_t)__bfloat16_as_ushort(l3) << 16) | __bfloat16_as_ushort(l2));
}

// ===========================================================================
// Projection GEMM on HMMA (wmma bf16, split precision):
//   out[m][n] = sum_k A[m][k] * W[n][k]   with  A=Ah+Al, W=Wh+Wl,
//   acc += Ah*Wh + Ah*Wl + Al*Wh  (fp32 accumulators)
// M=4096, N=1024, K=1024. Block tile 128x128, BK=32, 256 thr (8 warps).
// Warp grid 4x2: each warp computes 32x64 via 2x4 wmma 16x16x16 fragments.
// Output written directly in [b,h,s,hd] layout.
// ===========================================================================
#define BK 32
#define LDA 40   // bf16 elements per smem row (32 + 8 pad)

__global__ __launch_bounds__(256) void proj_wmma_kernel(
    const float* __restrict__ q, const float* __restrict__ k,
    const float* __restrict__ v, const float* __restrict__ wq,
    const float* __restrict__ wk, const float* __restrict__ wv)
{
    __shared__ __nv_bfloat16 Ah[128 * LDA];
    __shared__ __nv_bfloat16 Al[128 * LDA];
    __shared__ __nv_bfloat16 Wh[128 * LDA];
    __shared__ __nv_bfloat16 Wl[128 * LDA];

    const int z = blockIdx.z;
    const float* A = (z == 0) ? q : (z == 1) ? k : v;
    const float* W = (z == 0) ? wq : (z == 1) ? wk : wv;
    float* out = (z == 0) ? g_Q : (z == 1) ? g_K : g_V;

    const int tid = threadIdx.x;
    const int wid = tid >> 5;
    const int warp_m = wid >> 1;        // 0..3 -> 32-row slab
    const int warp_n = wid & 1;         // 0..1 -> 64-col slab
    const int m0 = blockIdx.y * 128;
    const int n0 = blockIdx.x * 128;

    wmma::fragment<wmma::accumulator, 16, 16, 16, float> acc[2][4];
    #pragma unroll
    for (int i = 0; i < 2; i++)
        #pragma unroll
        for (int j = 0; j < 4; j++) wmma::fill_fragment(acc[i][j], 0.0f);

    for (int k0 = 0; k0 < D_; k0 += BK) {
        // Load + split A and W chunks: 128x32 fp32 each = 1024 float4; 4/thread.
        #pragma unroll
        for (int it = 0; it < 4; it++) {
            int idx = it * 256 + tid;        // 0..1023
            int row = idx >> 3;              // 0..127
            int c = idx & 7;                 // float4 col
            uint2 hv, lv;
            float4 av = *reinterpret_cast<const float4*>(&A[(size_t)(m0 + row) * D_ + k0 + c * 4]);
            split4(av, hv, lv);
            *reinterpret_cast<uint2*>(&Ah[row * LDA + c * 4]) = hv;
            *reinterpret_cast<uint2*>(&Al[row * LDA + c * 4]) = lv;
            float4 wv4 = *reinterpret_cast<const float4*>(&W[(size_t)(n0 + row) * D_ + k0 + c * 4]);
            split4(wv4, hv, lv);
            *reinterpret_cast<uint2*>(&Wh[row * LDA + c * 4]) = hv;
            *reinterpret_cast<uint2*>(&Wl[row * LDA + c * 4]) = lv;
        }
        __syncthreads();

        #pragma unroll
        for (int kk = 0; kk < BK; kk += 16) {
            wmma::fragment<wmma::matrix_a, 16, 16, 16, __nv_bfloat16, wmma::row_major> aH[2], aL[2];
            wmma::fragment<wmma::matrix_b, 16, 16, 16, __nv_bfloat16, wmma::col_major> bH[4], bL[4];
            #pragma unroll
            for (int i = 0; i < 2; i++) {
                wmma::load_matrix_sync(aH[i], &Ah[(warp_m * 32 + i * 16) * LDA + kk], LDA);
                wmma::load_matrix_sync(aL[i], &Al[(warp_m * 32 + i * 16) * LDA + kk], LDA);
            }
            #pragma unroll
            for (int j = 0; j < 4; j++) {
                wmma::load_matrix_sync(bH[j], &Wh[(warp_n * 64 + j * 16) * LDA + kk], LDA);
                wmma::load_matrix_sync(bL[j], &Wl[(warp_n * 64 + j * 16) * LDA + kk], LDA);
            }
            #pragma unroll
            for (int i = 0; i < 2; i++)
                #pragma unroll
                for (int j = 0; j < 4; j++) {
                    wmma::mma_sync(acc[i][j], aH[i], bH[j], acc[i][j]);
                    wmma::mma_sync(acc[i][j], aH[i], bL[j], acc[i][j]);
                    wmma::mma_sync(acc[i][j], aL[i], bH[j], acc[i][j]);
                }
        }
        __syncthreads();
    }

    // Epilogue: store directly to [b,h,s,hd].
    const int b = m0 >> 11;
    #pragma unroll
    for (int i = 0; i < 2; i++) {
        int m = m0 + warp_m * 32 + i * 16;
        int s = m & (S_ - 1);
        #pragma unroll
        for (int j = 0; j < 4; j++) {
            int n = n0 + warp_n * 64 + j * 16;
            int h = n >> 6;
            int d0 = n & 63;
            float* dst = out + ((size_t)(b * H_ + h) * S_ + s) * HD_ + d0;
            wmma::store_matrix_sync(dst, acc[i][j], HD_, wmma::mem_row_major);
        }
    }
}

// ---------------------------------------------------------------------------
// Suffix sums of V: SufV[bh][s][d] = sum_{k>s} V[bh][k][d].
// 32 blocks (bh) x 64 threads (d); serial scan over s (coalesced loads).
// ---------------------------------------------------------------------------
__global__ __launch_bounds__(64) void suffix_kernel()
{
    const int bh = blockIdx.x;
    const int d = threadIdx.x;
    const float* Vp = g_V + (size_t)bh * S_ * HD_ + d;
    float* Sp = g_S + (size_t)bh * S_ * HD_ + d;
    float acc = 0.f;
    for (int s = S_ - 1; s >= 0; s--) {
        Sp[(size_t)s * HD_] = acc;
        acc += Vp[(size_t)s * HD_];
    }
}

// ---------------------------------------------------------------------------
// Attention, causal-only tiles + analytic masked tail.
// Reference zeroes (not -inf) the upper triangle pre-softmax, so each masked
// position has weight exp(0-m). With count = S-1-q masked entries:
//   Z = sum_{k<=q} exp(s_k - m) + count*exp(-m)
//   O = (sum_{k<=q} p_k v_k + exp(-m)*SufV[q]) / Z
// m initialized to 0 (valid stabilizer; math exact). Only kt<=qt tiles visited.
// ---------------------------------------------------------------------------
__global__ __launch_bounds__(256) void attn_kernel(float* __restrict__ out)
{
    extern __shared__ float sm[];
    float* Qs = sm;                 // [64][68] Qs[d][q]
    float* Ks = sm + 64 * 68;       // [64][68] Ks[d][k]
    float* Vs = sm + 2 * 64 * 68;   // [64][68] Vs[k][d]
    float* Ps = sm + 3 * 64 * 68;   // [64][68] Ps[k][q]

    const int tid = threadIdx.x;
    const int ty = tid >> 4, tx = tid & 15;
    const int bh = blockIdx.y;
    const int qt = blockIdx.x;
    const float* Qp = g_Q + (size_t)bh * S_ * HD_;
    const float* Kp = g_K + (size_t)bh * S_ * HD_;
    const float* Vp = g_V + (size_t)bh * S_ * HD_;

    const int lr = tid >> 2;
    const int c4 = tid & 3;

    #pragma unroll
    for (int j = 0; j < 4; j++) {
        int dcol = (c4 + 4 * j) * 4;
        float4 v = *reinterpret_cast<const float4*>(&Qp[(qt * 64 + lr) * HD_ + dcol]);
        Qs[(dcol + 0) * 68 + lr] = v.x;
        Qs[(dcol + 1) * 68 + lr] = v.y;
        Qs[(dcol + 2) * 68 + lr] = v.z;
        Qs[(dcol + 3) * 68 + lr] = v.w;
    }

    float m_i[4], l_i[4], o[4][4];
    #pragma unroll
    for (int i = 0; i < 4; i++) {
        m_i[i] = 0.f;       // includes the implicit zero-score bucket
        l_i[i] = 0.f;
        #pragma unroll
        for (int j = 0; j < 4; j++) o[i][j] = 0.f;
    }
    __syncthreads();

    const float scale = 0.125f;  // 1/sqrt(64)
    const int qbase = qt * 64 + ty * 4;

    for (int kt = 0; kt <= qt; kt++) {
        #pragma unroll
        for (int j = 0; j < 4; j++) {
            int dcol = (c4 + 4 * j) * 4;
            float4 kv = *reinterpret_cast<const float4*>(&Kp[(kt * 64 + lr) * HD_ + dcol]);
            Ks[(dcol + 0) * 68 + lr] = kv.x;
            Ks[(dcol + 1) * 68 + lr] = kv.y;
            Ks[(dcol + 2) * 68 + lr] = kv.z;
            Ks[(dcol + 3) * 68 + lr] = kv.w;
            float4 vv = *reinterpret_cast<const float4*>(&Vp[(kt * 64 + lr) * HD_ + dcol]);
            *reinterpret_cast<float4*>(&Vs[lr * 68 + dcol]) = vv;
        }
        __syncthreads();

        float sc[4][4];
        #pragma unroll
        for (int i = 0; i < 4; i++)
            #pragma unroll
            for (int j = 0; j < 4; j++) sc[i][j] = 0.f;
        #pragma unroll 16
        for (int kk = 0; kk < 64; kk++) {
            float4 a = *reinterpret_cast<const float4*>(&Qs[kk * 68 + ty * 4]);
            float4 b = *reinterpret_cast<const float4*>(&Ks[kk * 68 + tx * 4]);
            float ar[4] = {a.x, a.y, a.z, a.w};
            float br[4] = {b.x, b.y, b.z, b.w};
            #pragma unroll
            for (int i = 0; i < 4; i++)
                #pragma unroll
                for (int j = 0; j < 4; j++)
                    sc[i][j] = fmaf(ar[i], br[j], sc[i][j]);
        }

        const int kbase = kt * 64 + tx * 4;
        const bool diag = (kt == qt);

        #pragma unroll
        for (int i = 0; i < 4; i++) {
            float rm = -1e30f;
            bool ok[4];
            #pragma unroll
            for (int j = 0; j < 4; j++) {
                ok[j] = !diag || (kbase + j <= qbase + i);
                float v = sc[i][j] * scale;
                sc[i][j] = v;
                if (ok[j]) rm = fmaxf(rm, v);
            }
            rm = fmaxf(rm, __shfl_xor_sync(0xffffffffu, rm, 1));
            rm = fmaxf(rm, __shfl_xor_sync(0xffffffffu, rm, 2));
            rm = fmaxf(rm, __shfl_xor_sync(0xffffffffu, rm, 4));
            rm = fmaxf(rm, __shfl_xor_sync(0xffffffffu, rm, 8));
            float mnew = fmaxf(m_i[i], rm);
            float corr = __expf(m_i[i] - mnew);
            float rs = 0.f;
            #pragma unroll
            for (int j = 0; j < 4; j++) {
                float p = ok[j] ? __expf(sc[i][j] - mnew) : 0.f;
                sc[i][j] = p;
                rs += p;
            }
            rs += __shfl_xor_sync(0xffffffffu, rs, 1);
            rs += __shfl_xor_sync(0xffffffffu, rs, 2);
            rs += __shfl_xor_sync(0xffffffffu, rs, 4);
            rs += __shfl_xor_sync(0xffffffffu, rs, 8);
            l_i[i] = l_i[i] * corr + rs;
            m_i[i] = mnew;
            #pragma unroll
            for (int j = 0; j < 4; j++) o[i][j] *= corr;
        }

        #pragma unroll
        for (int i = 0; i < 4; i++)
            #pragma unroll
            for (int j = 0; j < 4; j++)
                Ps[(tx * 4 + j) * 68 + ty * 4 + i] = sc[i][j];
        __syncthreads();

        #pragma unroll 16
        for (int kk = 0; kk < 64; kk++) {
            float4 a = *reinterpret_cast<const float4*>(&Ps[kk * 68 + ty * 4]);
            float4 b = *reinterpret_cast<const float4*>(&Vs[kk * 68 + tx * 4]);
            float ar[4] = {a.x, a.y, a.z, a.w};
            float br[4] = {b.x, b.y, b.z, b.w};
            #pragma unroll
            for (int i = 0; i < 4; i++)
                #pragma unroll
                for (int j = 0; j < 4; j++)
                    o[i][j] = fmaf(ar[i], br[j], o[i][j]);
        }
        __syncthreads();
    }

    // Analytic masked tail + normalize + store.
    const int b = bh / H_;
    const int h = bh % H_;
    const float* Sufp = g_S + (size_t)bh * S_ * HD_;
    #pragma unroll
    for (int i = 0; i < 4; i++) {
        int q = qbase + i;
        float w0 = __expf(-m_i[i]);
        float cnt = (float)(S_ - 1 - q);
        float l = l_i[i] + cnt * w0;
        float4 suf = *reinterpret_cast<const float4*>(&Sufp[(size_t)q * HD_ + tx * 4]);
        float inv = 1.f / l;
        float4 vv = make_float4((o[i][0] + w0 * suf.x) * inv,
                                (o[i][1] + w0 * suf.y) * inv,
                                (o[i][2] + w0 * suf.z) * inv,
                                (o[i][3] + w0 * suf.w) * inv);
        *reinterpret_cast<float4*>(&out[((size_t)(b * S_ + q)) * D_ + h * HD_ + tx * 4]) = vv;
    }
}

// ---------------------------------------------------------------------------
extern "C" void kernel_launch(void* const* d_in, const int* in_sizes, int n_in,
                              void* d_out, int out_size)
{
    const float* q  = (const float*)d_in[0];
    const float* k  = (const float*)d_in[1];
    const float* v  = (const float*)d_in[2];
    const float* wq = (const float*)d_in[3];
    const float* wk = (const float*)d_in[4];
    const float* wv = (const float*)d_in[5];
    float* out = (float*)d_out;

    dim3 pgrid(D_ / 128, (B_ * S_) / 128, 3);   // (8, 32, 3)
    proj_wmma_kernel<<<pgrid, 256>>>(q, k, v, wq, wk, wv);

    suffix_kernel<<<B_ * H_, 64>>>();

    const int smem_bytes = 4 * 64 * 68 * 4;  // 69632
    cudaFuncSetAttribute(attn_kernel, cudaFuncAttributeMaxDynamicSharedMemorySize,
                         smem_bytes);
    attn_kernel<<<dim3(S_ / 64, B_ * H_), 256, smem_bytes>>>(out);
}

// round 6
// speedup vs baseline: 1.9196x; 1.7558x over previous
#include <cuda_runtime.h>
#include <cuda_bf16.h>
#include <mma.h>
#include <cstdint>
#include <math.h>

using namespace nvcuda;

#define B_  2
#define S_  2048
#define D_  1024
#define H_  16
#define HD_ 64

// Scratch: projected Q/K/V in [b,h,s,hd] layout + V suffix sums + partials.
__device__ float g_Q[B_*H_*S_*HD_];
__device__ float g_K[B_*H_*S_*HD_];
__device__ float g_V[B_*H_*S_*HD_];
__device__ float g_S[B_*H_*S_*HD_];     // SufV[bh][q][d] = sum_{k>q} V[bh][k][d]
__device__ float g_Part[32*32*64];      // per-(bh, seg) partial colsums

// ---------------------------------------------------------------------------
// helpers
// ---------------------------------------------------------------------------
__device__ __forceinline__ void split4(float4 a, uint2& hv, uint2& lv) {
    __nv_bfloat16 h0 = __float2bfloat16(a.x);
    __nv_bfloat16 h1 = __float2bfloat16(a.y);
    __nv_bfloat16 h2 = __float2bfloat16(a.z);
    __nv_bfloat16 h3 = __float2bfloat16(a.w);
    __nv_bfloat16 l0 = __float2bfloat16(a.x - __bfloat162float(h0));
    __nv_bfloat16 l1 = __float2bfloat16(a.y - __bfloat162float(h1));
    __nv_bfloat16 l2 = __float2bfloat16(a.z - __bfloat162float(h2));
    __nv_bfloat16 l3 = __float2bfloat16(a.w - __bfloat162float(h3));
    hv = make_uint2(((uint32_t)__bfloat16_as_ushort(h1) << 16) | __bfloat16_as_ushort(h0),
                    ((uint32_t)__bfloat16_as_ushort(h3) << 16) | __bfloat16_as_ushort(h2));
    lv = make_uint2(((uint32_t)__bfloat16_as_ushort(l1) << 16) | __bfloat16_as_ushort(l0),
                    ((uint32_t)__bfloat16_as_ushort(l3) << 16) | __bfloat16_as_ushort(l2));
}

// Fast exp on the FMA pipe (no MUFU): exp(s) = 2^(s*log2e).
// Magic-number round; degree-5 poly of 2^f on [-0.5,0.5]; rel err ~2.4e-6.
__device__ __forceinline__ float fexp(float s) {
    float x = s * 1.4426950408889634f;
    float j = x + 12582912.0f;                 // 1.5 * 2^23
    float xi = j - 12582912.0f;
    float f = x - xi;                          // [-0.5, 0.5]
    int e = __float_as_int(j) - 0x4B400000;    // round(x)
    float p = 1.3333558e-3f;
    p = fmaf(p, f, 9.6181291e-3f);
    p = fmaf(p, f, 5.5504109e-2f);
    p = fmaf(p, f, 2.4022651e-1f);
    p = fmaf(p, f, 6.9314718e-1f);
    p = fmaf(p, f, 1.0f);
    return p * __int_as_float((e + 127) << 23);
}

// ===========================================================================
// Projection GEMM on HMMA (wmma bf16, split precision) — as in R4 (passing).
// ===========================================================================
#define BK 32
#define LDA 40

__global__ __launch_bounds__(256) void proj_wmma_kernel(
    const float* __restrict__ q, const float* __restrict__ k,
    const float* __restrict__ v, const float* __restrict__ wq,
    const float* __restrict__ wk, const float* __restrict__ wv)
{
    __shared__ __nv_bfloat16 Ah[128 * LDA];
    __shared__ __nv_bfloat16 Al[128 * LDA];
    __shared__ __nv_bfloat16 Wh[128 * LDA];
    __shared__ __nv_bfloat16 Wl[128 * LDA];

    const int z = blockIdx.z;
    const float* A = (z == 0) ? q : (z == 1) ? k : v;
    const float* W = (z == 0) ? wq : (z == 1) ? wk : wv;
    float* out = (z == 0) ? g_Q : (z == 1) ? g_K : g_V;

    const int tid = threadIdx.x;
    const int wid = tid >> 5;
    const int warp_m = wid >> 1;
    const int warp_n = wid & 1;
    const int m0 = blockIdx.y * 128;
    const int n0 = blockIdx.x * 128;

    wmma::fragment<wmma::accumulator, 16, 16, 16, float> acc[2][4];
    #pragma unroll
    for (int i = 0; i < 2; i++)
        #pragma unroll
        for (int j = 0; j < 4; j++) wmma::fill_fragment(acc[i][j], 0.0f);

    for (int k0 = 0; k0 < D_; k0 += BK) {
        #pragma unroll
        for (int it = 0; it < 4; it++) {
            int idx = it * 256 + tid;
            int row = idx >> 3;
            int c = idx & 7;
            uint2 hv, lv;
            float4 av = *reinterpret_cast<const float4*>(&A[(size_t)(m0 + row) * D_ + k0 + c * 4]);
            split4(av, hv, lv);
            *reinterpret_cast<uint2*>(&Ah[row * LDA + c * 4]) = hv;
            *reinterpret_cast<uint2*>(&Al[row * LDA + c * 4]) = lv;
            float4 wv4 = *reinterpret_cast<const float4*>(&W[(size_t)(n0 + row) * D_ + k0 + c * 4]);
            split4(wv4, hv, lv);
            *reinterpret_cast<uint2*>(&Wh[row * LDA + c * 4]) = hv;
            *reinterpret_cast<uint2*>(&Wl[row * LDA + c * 4]) = lv;
        }
        __syncthreads();

        #pragma unroll
        for (int kk = 0; kk < BK; kk += 16) {
            wmma::fragment<wmma::matrix_a, 16, 16, 16, __nv_bfloat16, wmma::row_major> aH[2], aL[2];
            wmma::fragment<wmma::matrix_b, 16, 16, 16, __nv_bfloat16, wmma::col_major> bH[4], bL[4];
            #pragma unroll
            for (int i = 0; i < 2; i++) {
                wmma::load_matrix_sync(aH[i], &Ah[(warp_m * 32 + i * 16) * LDA + kk], LDA);
                wmma::load_matrix_sync(aL[i], &Al[(warp_m * 32 + i * 16) * LDA + kk], LDA);
            }
            #pragma unroll
            for (int j = 0; j < 4; j++) {
                wmma::load_matrix_sync(bH[j], &Wh[(warp_n * 64 + j * 16) * LDA + kk], LDA);
                wmma::load_matrix_sync(bL[j], &Wl[(warp_n * 64 + j * 16) * LDA + kk], LDA);
            }
            #pragma unroll
            for (int i = 0; i < 2; i++)
                #pragma unroll
                for (int j = 0; j < 4; j++) {
                    wmma::mma_sync(acc[i][j], aH[i], bH[j], acc[i][j]);
                    wmma::mma_sync(acc[i][j], aH[i], bL[j], acc[i][j]);
                    wmma::mma_sync(acc[i][j], aL[i], bH[j], acc[i][j]);
                }
        }
        __syncthreads();
    }

    const int b = m0 >> 11;
    #pragma unroll
    for (int i = 0; i < 2; i++) {
        int m = m0 + warp_m * 32 + i * 16;
        int s = m & (S_ - 1);
        #pragma unroll
        for (int j = 0; j < 4; j++) {
            int n = n0 + warp_n * 64 + j * 16;
            int h = n >> 6;
            int d0 = n & 63;
            float* dst = out + ((size_t)(b * H_ + h) * S_ + s) * HD_ + d0;
            wmma::store_matrix_sync(dst, acc[i][j], HD_, wmma::mem_row_major);
        }
    }
}

// ---------------------------------------------------------------------------
// Parallel suffix sums of V (3 phases).
// ---------------------------------------------------------------------------
__global__ __launch_bounds__(64) void suffix_k1()
{
    const int bh = blockIdx.y, seg = blockIdx.x, d = threadIdx.x;
    const float* Vp = g_V + (size_t)bh * S_ * HD_ + (size_t)seg * 64 * HD_ + d;
    float acc = 0.f;
    #pragma unroll 8
    for (int s = 0; s < 64; s++) acc += Vp[(size_t)s * HD_];
    g_Part[(bh * 32 + seg) * 64 + d] = acc;
}
__global__ __launch_bounds__(64) void suffix_k2()
{
    const int bh = blockIdx.x, d = threadIdx.x;
    float* P = g_Part + bh * 32 * 64 + d;
    float acc = 0.f;
    for (int seg = 31; seg >= 0; seg--) {
        float t = P[seg * 64];
        P[seg * 64] = acc;
        acc += t;
    }
}
__global__ __launch_bounds__(64) void suffix_k3()
{
    const int bh = blockIdx.y, seg = blockIdx.x, d = threadIdx.x;
    const float* Vp = g_V + (size_t)bh * S_ * HD_ + (size_t)seg * 64 * HD_ + d;
    float* Sp = g_S + (size_t)bh * S_ * HD_ + (size_t)seg * 64 * HD_ + d;
    float acc = g_Part[(bh * 32 + seg) * 64 + d];
    for (int s = 63; s >= 0; s--) {
        Sp[(size_t)s * HD_] = acc;
        acc += Vp[(size_t)s * HD_];
    }
}

// ===========================================================================
// Attention on wmma bf16, FULL split precision on all operands:
//   S = Qh.Kh + Qh.Kl + Ql.Kh ; P = exp(S/8) masked ; split P
//   O += Ph.Vh + Ph.Vl + Pl.Vh   (fp32 accumulators everywhere)
// Zero-mask reference => m=0 stabilizer:
//   Z[q] = sum_{k<=q} exp(s_k) + (S-1-q)
//   O[q] = (sum_{k<=q} exp(s_k) v_k + SufV[q]) / Z[q]
// Block: 64 q-rows, 256 thr (8 warps, warp = 16x32 sub-tile); kt <= qt only.
// ===========================================================================
#define ATT_LD 72
#define SS_LD  68
// 8 bf16 tiles (Qh,Ql,Kh,Kl,Ph,Pl,Vh,Vl) + Ss + Zs
#define ATT_SMEM (8*64*ATT_LD*2 + 64*SS_LD*4 + 64*4 + 128)

__global__ __launch_bounds__(256) void attn_wmma_kernel(float* __restrict__ out)
{
    extern __shared__ char smem_raw[];
    __nv_bfloat16* Qh = (__nv_bfloat16*)smem_raw;
    __nv_bfloat16* Ql = Qh + 64 * ATT_LD;
    __nv_bfloat16* Kh = Ql + 64 * ATT_LD;
    __nv_bfloat16* Kl = Kh + 64 * ATT_LD;
    __nv_bfloat16* Ph = Kl + 64 * ATT_LD;
    __nv_bfloat16* Pl = Ph + 64 * ATT_LD;
    __nv_bfloat16* Vh = Pl + 64 * ATT_LD;
    __nv_bfloat16* Vl = Vh + 64 * ATT_LD;
    float* Ss = (float*)(Vl + 64 * ATT_LD);
    float* Zs = Ss + 64 * SS_LD;

    const int tid = threadIdx.x;
    const int wid = tid >> 5;
    const int qt = blockIdx.x, bh = blockIdx.y;
    const float* Qp = g_Q + (size_t)bh * S_ * HD_;
    const float* Kp = g_K + (size_t)bh * S_ * HD_;
    const float* Vp = g_V + (size_t)bh * S_ * HD_;

    // Load + split Q tile (64x64): 1024 float4, 4/thread.
    #pragma unroll
    for (int it = 0; it < 4; it++) {
        int idx = it * 256 + tid;
        int r = idx >> 4, c = idx & 15;
        float4 a = *reinterpret_cast<const float4*>(&Qp[(qt * 64 + r) * HD_ + c * 4]);
        uint2 hv, lv; split4(a, hv, lv);
        *reinterpret_cast<uint2*>(&Qh[r * ATT_LD + c * 4]) = hv;
        *reinterpret_cast<uint2*>(&Ql[r * ATT_LD + c * 4]) = lv;
    }
    if (tid < 64) Zs[tid] = 0.f;

    wmma::fragment<wmma::accumulator, 16, 16, 16, float> ofrag[2];
    wmma::fill_fragment(ofrag[0], 0.f);
    wmma::fill_fragment(ofrag[1], 0.f);

    const int qrow = (wid >> 1) * 16;
    const int kcol = (wid & 1) * 32;
    __syncthreads();

    for (int kt = 0; kt <= qt; kt++) {
        // Load K, V tiles (both split).
        #pragma unroll
        for (int it = 0; it < 4; it++) {
            int idx = it * 256 + tid;
            int r = idx >> 4, c = idx & 15;
            uint2 hv, lv;
            float4 kv = *reinterpret_cast<const float4*>(&Kp[(kt * 64 + r) * HD_ + c * 4]);
            split4(kv, hv, lv);
            *reinterpret_cast<uint2*>(&Kh[r * ATT_LD + c * 4]) = hv;
            *reinterpret_cast<uint2*>(&Kl[r * ATT_LD + c * 4]) = lv;
            float4 vv = *reinterpret_cast<const float4*>(&Vp[(kt * 64 + r) * HD_ + c * 4]);
            split4(vv, hv, lv);
            *reinterpret_cast<uint2*>(&Vh[r * ATT_LD + c * 4]) = hv;
            *reinterpret_cast<uint2*>(&Vl[r * ATT_LD + c * 4]) = lv;
        }
        __syncthreads();

        // S = Q.K^T, split 3-term.
        wmma::fragment<wmma::accumulator, 16, 16, 16, float> sfrag[2];
        wmma::fill_fragment(sfrag[0], 0.f);
        wmma::fill_fragment(sfrag[1], 0.f);
        #pragma unroll
        for (int kk = 0; kk < 64; kk += 16) {
            wmma::fragment<wmma::matrix_a, 16, 16, 16, __nv_bfloat16, wmma::row_major> aH, aL;
            wmma::load_matrix_sync(aH, &Qh[qrow * ATT_LD + kk], ATT_LD);
            wmma::load_matrix_sync(aL, &Ql[qrow * ATT_LD + kk], ATT_LD);
            #pragma unroll
            for (int c = 0; c < 2; c++) {
                wmma::fragment<wmma::matrix_b, 16, 16, 16, __nv_bfloat16, wmma::col_major> bH, bL;
                wmma::load_matrix_sync(bH, &Kh[(kcol + c * 16) * ATT_LD + kk], ATT_LD);
                wmma::load_matrix_sync(bL, &Kl[(kcol + c * 16) * ATT_LD + kk], ATT_LD);
                wmma::mma_sync(sfrag[c], aH, bH, sfrag[c]);
                wmma::mma_sync(sfrag[c], aH, bL, sfrag[c]);
                wmma::mma_sync(sfrag[c], aL, bH, sfrag[c]);
            }
        }
        wmma::store_matrix_sync(&Ss[qrow * SS_LD + kcol], sfrag[0], SS_LD, wmma::mem_row_major);
        wmma::store_matrix_sync(&Ss[qrow * SS_LD + kcol + 16], sfrag[1], SS_LD, wmma::mem_row_major);
        __syncthreads();

        // p = exp(s/8) (masked -> 0); accumulate Z; write split P.
        {
            const int r = tid >> 2;
            const int c0 = (tid & 3) * 16;
            const int qglob = qt * 64 + r;
            const int kglob0 = kt * 64 + c0;
            const bool diag = (kt == qt);
            float rs = 0.f;
            #pragma unroll
            for (int j = 0; j < 16; j++) {
                float s = Ss[r * SS_LD + c0 + j] * 0.125f;
                bool okv = !diag || (kglob0 + j <= qglob);
                float p = okv ? fexp(s) : 0.f;
                rs += p;
                __nv_bfloat16 ph = __float2bfloat16(p);
                __nv_bfloat16 pl = __float2bfloat16(p - __bfloat162float(ph));
                Ph[r * ATT_LD + c0 + j] = ph;
                Pl[r * ATT_LD + c0 + j] = pl;
            }
            rs += __shfl_xor_sync(0xffffffffu, rs, 1);
            rs += __shfl_xor_sync(0xffffffffu, rs, 2);
            if ((tid & 3) == 0) Zs[r] += rs;
        }
        __syncthreads();

        // O += Ph.Vh + Ph.Vl + Pl.Vh
        #pragma unroll
        for (int kk = 0; kk < 64; kk += 16) {
            wmma::fragment<wmma::matrix_a, 16, 16, 16, __nv_bfloat16, wmma::row_major> apH, apL;
            wmma::load_matrix_sync(apH, &Ph[qrow * ATT_LD + kk], ATT_LD);
            wmma::load_matrix_sync(apL, &Pl[qrow * ATT_LD + kk], ATT_LD);
            #pragma unroll
            for (int c = 0; c < 2; c++) {
                wmma::fragment<wmma::matrix_b, 16, 16, 16, __nv_bfloat16, wmma::row_major> bvH, bvL;
                wmma::load_matrix_sync(bvH, &Vh[kk * ATT_LD + kcol + c * 16], ATT_LD);
                wmma::load_matrix_sync(bvL, &Vl[kk * ATT_LD + kcol + c * 16], ATT_LD);
                wmma::mma_sync(ofrag[c], apH, bvH, ofrag[c]);
                wmma::mma_sync(ofrag[c], apH, bvL, ofrag[c]);
                wmma::mma_sync(ofrag[c], apL, bvH, ofrag[c]);
            }
        }
        __syncthreads();
    }

    // Stage O to smem, then epilogue: add suffix tail, normalize, store.
    wmma::store_matrix_sync(&Ss[qrow * SS_LD + kcol], ofrag[0], SS_LD, wmma::mem_row_major);
    wmma::store_matrix_sync(&Ss[qrow * SS_LD + kcol + 16], ofrag[1], SS_LD, wmma::mem_row_major);
    __syncthreads();

    const int b = bh / H_, h = bh % H_;
    const float* Sufp = g_S + (size_t)bh * S_ * HD_;
    {
        const int r = tid >> 2;
        const int c0 = (tid & 3) * 16;
        const int q = qt * 64 + r;
        float Zr = Zs[r] + (float)(S_ - 1 - q);
        float inv = 1.f / Zr;
        float* dst = out + ((size_t)(b * S_ + q)) * D_ + h * HD_ + c0;
        const float* suf = &Sufp[(size_t)q * HD_ + c0];
        #pragma unroll
        for (int j = 0; j < 16; j += 4) {
            float4 sv = *reinterpret_cast<const float4*>(&suf[j]);
            float4 ov = make_float4(
                (Ss[r * SS_LD + c0 + j + 0] + sv.x) * inv,
                (Ss[r * SS_LD + c0 + j + 1] + sv.y) * inv,
                (Ss[r * SS_LD + c0 + j + 2] + sv.z) * inv,
                (Ss[r * SS_LD + c0 + j + 3] + sv.w) * inv);
            *reinterpret_cast<float4*>(&dst[j]) = ov;
        }
    }
}

// ---------------------------------------------------------------------------
extern "C" void kernel_launch(void* const* d_in, const int* in_sizes, int n_in,
                              void* d_out, int out_size)
{
    const float* q  = (const float*)d_in[0];
    const float* k  = (const float*)d_in[1];
    const float* v  = (const float*)d_in[2];
    const float* wq = (const float*)d_in[3];
    const float* wk = (const float*)d_in[4];
    const float* wv = (const float*)d_in[5];
    float* out = (float*)d_out;

    dim3 pgrid(D_ / 128, (B_ * S_) / 128, 3);
    proj_wmma_kernel<<<pgrid, 256>>>(q, k, v, wq, wk, wv);

    suffix_k1<<<dim3(32, B_ * H_), 64>>>();
    suffix_k2<<<B_ * H_, 64>>>();
    suffix_k3<<<dim3(32, B_ * H_), 64>>>();

    cudaFuncSetAttribute(attn_wmma_kernel,
                         cudaFuncAttributeMaxDynamicSharedMemorySize, ATT_SMEM);
    attn_wmma_kernel<<<dim3(S_ / 64, B_ * H_), 256, ATT_SMEM>>>(out);
}